// round 10
// baseline (speedup 1.0000x reference)
#include <cuda_runtime.h>
#include <math.h>

// Problem constants
#define BB     256
#define TT     4096
#define NN     8
#define TWO_N  16
#define PP     144      // 2N + 2N^2
#define HH     64

// latent/dlatent table: 328 segments, lerp error ~4e-6 << 1e-3.
// Row stride 36 floats: bank-group = 4*i0 mod 32 -> 8 groups (max spread for 16B loads).
#define TPTS   329
#define TSEG   328
#define ROWF   36
#define ROWF4  9

// 4 blocks per batch row, 256 thr, 4 samples/thread
#define GRID_MAIN 1024
#define BLK       256
#define SPT       4

__device__ __align__(16) float  g_table[TPTS * ROWF];
__device__ double   g_partd[GRID_MAIN];
__device__ double   g_parts[GRID_MAIN];
__device__ unsigned g_cnt = 0;    // self-resetting completion counter

// ---- packed f32x2 helpers ------------------------------------------------
typedef unsigned long long u64;
__device__ __forceinline__ u64 fma2(u64 a, u64 b, u64 c) {
    u64 d; asm("fma.rn.f32x2 %0, %1, %2, %3;" : "=l"(d) : "l"(a), "l"(b), "l"(c)); return d;
}
__device__ __forceinline__ u64 add2(u64 a, u64 b) {
    u64 d; asm("add.rn.f32x2 %0, %1, %2;" : "=l"(d) : "l"(a), "l"(b)); return d;
}
__device__ __forceinline__ u64 mul2(u64 a, u64 b) {
    u64 d; asm("mul.rn.f32x2 %0, %1, %2;" : "=l"(d) : "l"(a), "l"(b)); return d;
}
__device__ __forceinline__ u64 pack2(float lo, float hi) {
    u64 d; asm("mov.b64 %0, {%1, %2};" : "=l"(d) : "f"(lo), "f"(hi)); return d;
}
__device__ __forceinline__ void unpack2(u64 v, float& lo, float& hi) {
    asm("mov.b64 {%0, %1}, %2;" : "=f"(lo), "=f"(hi) : "l"(v));
}
union F4 { float4 v; u64 u[2]; };

// ---------------------------------------------------------------------------
// Kernel 1: build latent/dlatent table (4 points / 256-thread block)
// ---------------------------------------------------------------------------
__global__ void table_kernel(const float* __restrict__ W1, const float* __restrict__ b1,
                             const float* __restrict__ W2, const float* __restrict__ b2) {
    __shared__ float sW2[HH * TWO_N];
    __shared__ float sb2[TWO_N];
    __shared__ float sh[4][HH];
    __shared__ float sdh[4][HH];
    const int tid = threadIdx.x;
    const int sub = tid >> 6;
    const int k   = tid & 63;
    const int m   = blockIdx.x * 4 + sub;

    for (int i = tid; i < HH * TWO_N; i += BLK) sW2[i] = W2[i];
    if (tid < TWO_N) sb2[tid] = b2[tid];

    float tt = (float)m * (1.0f / (float)TSEG);
    float w  = W1[k];
    float h  = tanhf(fmaf(tt, w, b1[k]));
    sh[sub][k]  = h;
    sdh[sub][k] = (1.0f - h * h) * w;
    __syncthreads();

    if (k < TWO_N && m < TPTS) {
        float lat = sb2[k];
        float dl  = 0.0f;
#pragma unroll
        for (int j = 0; j < HH; j++) {
            float w2 = sW2[j * TWO_N + k];
            lat = fmaf(sh[sub][j],  w2, lat);
            dl  = fmaf(sdh[sub][j], w2, dl);
        }
        g_table[m * ROWF + k]         = lat;
        g_table[m * ROWF + TWO_N + k] = dl;
    }
}

// ---------------------------------------------------------------------------
// Kernel 2: main loss + fused final reduction (last block)
// ---------------------------------------------------------------------------
__global__ void __launch_bounds__(BLK, 4)
main_kernel(const float* __restrict__ t_in,
            const float* __restrict__ x_target,
            const float* __restrict__ params_pred,
            const float* __restrict__ params_target,
            const float* __restrict__ ic_pred,
            const float* __restrict__ ic_target,
            float* __restrict__ out) {
    __shared__ __align__(16) float s_tab[TPTS * ROWF];     // 47376 B (aliased for final red.)
    __shared__ __align__(16) float s_gmu[TWO_N];           // g[8] | mu[8]
    __shared__ __align__(16) float s_piT[NN * NN];         // PiT[j][i]
    __shared__ __align__(16) float s_gaT[NN * NN];         // GaT[j][i]
    __shared__ double s_red[BLK / 32];
    __shared__ double s_sup[40];
    __shared__ int    s_flag;

    const int tid   = threadIdx.x;
    const int b     = blockIdx.x >> 2;
    const int chunk = blockIdx.x & 3;

    // stage table (float4), params (transposed matrices)
    {
        const float4* src = (const float4*)g_table;
        float4*       dst = (float4*)s_tab;
        for (int i = tid; i < TPTS * ROWF4; i += BLK) dst[i] = src[i];
    }
    if (tid < TWO_N) s_gmu[tid] = params_pred[b * PP + tid];
    if (tid >= 64 && tid < 192) {
        int r   = tid & 63;
        int mat = (tid >> 6) & 1;       // 0=Pi (tid 64..127), 1=Ga (tid 128..191)
        int i   = r >> 3, j = r & 7;
        float v = params_pred[b * PP + TWO_N + mat * 64 + i * NN + j];
        if (mat == 0) s_piT[j * NN + i] = v; else s_gaT[j * NN + i] = v;
    }
    __syncthreads();

    // prefetch all t values
    float tv[SPT];
#pragma unroll
    for (int it = 0; it < SPT; it++)
        tv[it] = t_in[b * TT + chunk * (SPT * BLK) + it * BLK + tid];

    const u64 NEG1 = pack2(-1.0f, -1.0f);
    float acc = 0.0f;
    u64   acc2 = pack2(0.0f, 0.0f);

#pragma unroll
    for (int it = 0; it < SPT; it++) {
        const int t = chunk * (SPT * BLK) + it * BLK + tid;

        // index + lerp
        float u  = tv[it] * (float)TSEG;
        int   i0 = (int)u;
        i0 = min(max(i0, 0), TPTS - 2);
        const float f = u - (float)i0;
        const u64 f2  = pack2(f, f);
        const u64 mf2 = pack2(-f, -f);

        const float4* p0 = (const float4*)s_tab + i0 * ROWF4;
        float L[TWO_N], Da[NN], Dq[NN];
#pragma unroll
        for (int q = 0; q < 4; q++) {        // latent: 16 values
            F4 a0, a1, r;
            a0.v = p0[q]; a1.v = p0[q + ROWF4];
            r.u[0] = fma2(f2, a1.u[0], fma2(mf2, a0.u[0], a0.u[0]));
            r.u[1] = fma2(f2, a1.u[1], fma2(mf2, a0.u[1], a0.u[1]));
            L[q*4+0] = r.v.x; L[q*4+1] = r.v.y; L[q*4+2] = r.v.z; L[q*4+3] = r.v.w;
        }
#pragma unroll
        for (int q = 0; q < 2; q++) {        // dlatent a-part
            F4 a0, a1, r;
            a0.v = p0[4 + q]; a1.v = p0[4 + q + ROWF4];
            r.u[0] = fma2(f2, a1.u[0], fma2(mf2, a0.u[0], a0.u[0]));
            r.u[1] = fma2(f2, a1.u[1], fma2(mf2, a0.u[1], a0.u[1]));
            Da[q*4+0] = r.v.x; Da[q*4+1] = r.v.y; Da[q*4+2] = r.v.z; Da[q*4+3] = r.v.w;
        }
#pragma unroll
        for (int q = 0; q < 2; q++) {        // dlatent q-part
            F4 a0, a1, r;
            a0.v = p0[6 + q]; a1.v = p0[6 + q + ROWF4];
            r.u[0] = fma2(f2, a1.u[0], fma2(mf2, a0.u[0], a0.u[0]));
            r.u[1] = fma2(f2, a1.u[1], fma2(mf2, a0.u[1], a0.u[1]));
            Dq[q*4+0] = r.v.x; Dq[q*4+1] = r.v.y; Dq[q*4+2] = r.v.z; Dq[q*4+3] = r.v.w;
        }

        // observables: x = relu(q - mu); gated tangent (L[8:16], Dq die here)
        float x[NN], dxt[NN];
#pragma unroll
        for (int i = 0; i < NN; i++) {
            float z   = L[NN + i] - s_gmu[NN + i];
            bool  pos = z > 0.0f;
            x[i]   = pos ? z : 0.0f;
            dxt[i] = pos ? Dq[i] : 0.0f;
        }

        // data loss (xt regs retire before matvec)
        const float* xt = x_target + (size_t)b * TWO_N * TT + t;
#pragma unroll
        for (int c = 0; c < NN; c++) {
            float d = L[c] - xt[c * TT];
            acc = fmaf(d, d, acc);
        }
#pragma unroll
        for (int c = 0; c < NN; c++) {
            float d = x[c] - xt[(NN + c) * TT];
            acc = fmaf(d, d, acc);
        }

        // physics: packed matvecs over transposed rows (broadcast LDS.128)
        u64 pix[4], ga[4];
#pragma unroll
        for (int p = 0; p < 4; p++) { pix[p] = 0ULL; ga[p] = 0ULL; }
#pragma unroll
        for (int j = 0; j < NN; j++) {
            F4 rp0, rp1, rg0, rg1;
            rp0.v = ((const float4*)s_piT)[2*j];
            rp1.v = ((const float4*)s_piT)[2*j + 1];
            rg0.v = ((const float4*)s_gaT)[2*j];
            rg1.v = ((const float4*)s_gaT)[2*j + 1];
            u64 x2j = pack2(x[j], x[j]);
            u64 a2j = pack2(L[j], L[j]);
            pix[0] = fma2(x2j, rp0.u[0], pix[0]);
            pix[1] = fma2(x2j, rp0.u[1], pix[1]);
            pix[2] = fma2(x2j, rp1.u[0], pix[2]);
            pix[3] = fma2(x2j, rp1.u[1], pix[3]);
            ga[0]  = fma2(a2j, rg0.u[0], ga[0]);
            ga[1]  = fma2(a2j, rg0.u[1], ga[1]);
            ga[2]  = fma2(a2j, rg1.u[0], ga[2]);
            ga[3]  = fma2(a2j, rg1.u[1], ga[3]);
        }
        // residuals: e1 = Da - g - pix + L_a ; e2 = dxt - ga*(mu - x)
#pragma unroll
        for (int p = 0; p < 4; p++) {
            u64 g2  = *(const u64*)(s_gmu + 2*p);
            u64 m2  = *(const u64*)(s_gmu + NN + 2*p);
            u64 l2  = pack2(L[2*p], L[2*p+1]);
            u64 d2  = pack2(Da[2*p], Da[2*p+1]);
            u64 x2  = pack2(x[2*p], x[2*p+1]);
            u64 dt2 = pack2(dxt[2*p], dxt[2*p+1]);
            u64 s   = fma2(NEG1, g2, d2);       // Da - g
            s       = fma2(NEG1, pix[p], s);    // - pix
            s       = add2(s, l2);              // + L_a
            acc2    = fma2(s, s, acc2);
            u64 mm  = fma2(NEG1, x2, m2);       // mu - x
            u64 pr  = mul2(ga[p], mm);
            u64 e   = fma2(NEG1, pr, dt2);      // dxt - ga*(mu-x)
            acc2    = fma2(e, e, acc2);
        }
    }

    // supervised slice: 40 elements/block covers B*160 = 40960 exactly
    if (tid < 40) {
        int idx = blockIdx.x * 40 + tid;
        int row = idx / 160;
        int col = idx - row * 160;
        float d;
        if (col < PP) d = params_pred[row * PP + col] - params_target[row * PP + col];
        else          d = ic_pred[row * TWO_N + (col - PP)] - ic_target[row * TWO_N + (col - PP)];
        s_sup[tid] = (double)d * (double)d;
    }

    // deterministic block reduction
    float alo, ahi; unpack2(acc2, alo, ahi);
    double v = (double)(acc + alo + ahi);
#pragma unroll
    for (int off = 16; off > 0; off >>= 1)
        v += __shfl_down_sync(0xFFFFFFFFu, v, off);
    if ((tid & 31) == 0) s_red[tid >> 5] = v;
    __syncthreads();
    if (tid == 0) {
        double s = 0.0;
#pragma unroll
        for (int w = 0; w < BLK / 32; w++) s += s_red[w];
        g_partd[blockIdx.x] = s;
        double sp = 0.0;
        for (int j = 0; j < 40; j++) sp += s_sup[j];
        g_parts[blockIdx.x] = sp;
        __threadfence();
        unsigned old = atomicAdd(&g_cnt, 1u);
        s_flag = (old == GRID_MAIN - 1) ? 1 : 0;
    }
    __syncthreads();

    // last block: deterministic final reduction (aliases s_tab as doubles)
    if (s_flag) {
        __threadfence();
        double* s1 = (double*)s_tab;
        double* s2 = s1 + (BLK / 32);
        double a = 0.0, c = 0.0;
        for (int i = tid; i < GRID_MAIN; i += BLK) { a += g_partd[i]; c += g_parts[i]; }
#pragma unroll
        for (int off = 16; off > 0; off >>= 1) {
            a += __shfl_down_sync(0xFFFFFFFFu, a, off);
            c += __shfl_down_sync(0xFFFFFFFFu, c, off);
        }
        if ((tid & 31) == 0) { s1[tid >> 5] = a; s2[tid >> 5] = c; }
        __syncthreads();
        if (tid == 0) {
            double t1 = 0.0, t2 = 0.0;
#pragma unroll
            for (int w = 0; w < BLK / 32; w++) { t1 += s1[w]; t2 += s2[w]; }
            double loss = t1 / (double)((size_t)BB * TWO_N * TT)
                        + t2 / (double)(BB * 160);
            out[0] = (float)loss;
            g_cnt  = 0;      // reset for next (graph-replayed) launch
        }
    }
}

// ---------------------------------------------------------------------------
extern "C" void kernel_launch(void* const* d_in, const int* in_sizes, int n_in,
                              void* d_out, int out_size) {
    const float* t_in          = (const float*)d_in[0];
    const float* x_target      = (const float*)d_in[1];
    const float* params_pred   = (const float*)d_in[2];
    const float* params_target = (const float*)d_in[3];
    const float* ic_pred       = (const float*)d_in[4];
    const float* ic_target     = (const float*)d_in[5];
    const float* W1            = (const float*)d_in[6];
    const float* b1            = (const float*)d_in[7];
    const float* W2            = (const float*)d_in[8];
    const float* b2            = (const float*)d_in[9];

    table_kernel<<<(TPTS + 3) / 4, BLK>>>(W1, b1, W2, b2);
    main_kernel<<<GRID_MAIN, BLK>>>(t_in, x_target, params_pred, params_target,
                                    ic_pred, ic_target, (float*)d_out);
}

// round 11
// speedup vs baseline: 2.3050x; 2.3050x over previous
#include <cuda_runtime.h>
#include <math.h>

// Problem constants
#define BB     256
#define TT     4096
#define NN     8
#define TWO_N  16
#define PP     144      // 2N + 2N^2
#define HH     64

// latent/dlatent base table over tt in [0,1): 328 segments, lerp err ~4e-6
#define TPTS   329
#define TSEG   328
#define ROWF   36       // base table row stride (floats)

// per-b expanded table row: s[16] | ur[8] | vr[8] | psi | pad3  = 36 floats
#define ROWB   36
#define ROWB4  9

// 4 blocks per batch row, 256 thr, 4 samples/thread
#define GRID_MAIN 1024
#define BLK       256
#define SPT       4

__device__ __align__(16) float g_table[TPTS * ROWF];            // latent|dlatent
__device__ __align__(16) float g_btab[BB * TPTS * ROWB];        // 12.1 MB per-b table
__device__ double   g_partd[GRID_MAIN];
__device__ double   g_parts[GRID_MAIN];
__device__ unsigned g_cnt = 0;

// ---- packed f32x2 helpers ------------------------------------------------
typedef unsigned long long u64;
__device__ __forceinline__ u64 fma2(u64 a, u64 b, u64 c) {
    u64 d; asm("fma.rn.f32x2 %0, %1, %2, %3;" : "=l"(d) : "l"(a), "l"(b), "l"(c)); return d;
}
__device__ __forceinline__ u64 pack2(float lo, float hi) {
    u64 d; asm("mov.b64 %0, {%1, %2};" : "=l"(d) : "f"(lo), "f"(hi)); return d;
}
union F4 { float4 v; u64 u[2]; };

// ---------------------------------------------------------------------------
// Kernel 1: latent/dlatent vs tt (4 points / 256-thread block)
// ---------------------------------------------------------------------------
__global__ void table_kernel(const float* __restrict__ W1, const float* __restrict__ b1,
                             const float* __restrict__ W2, const float* __restrict__ b2) {
    __shared__ float sW2[HH * TWO_N];
    __shared__ float sb2[TWO_N];
    __shared__ float sh[4][HH];
    __shared__ float sdh[4][HH];
    const int tid = threadIdx.x;
    const int sub = tid >> 6;
    const int k   = tid & 63;
    const int m   = blockIdx.x * 4 + sub;

    for (int i = tid; i < HH * TWO_N; i += BLK) sW2[i] = W2[i];
    if (tid < TWO_N) sb2[tid] = b2[tid];

    float tt = (float)m * (1.0f / (float)TSEG);
    float w  = W1[k];
    float h  = tanhf(fmaf(tt, w, b1[k]));
    sh[sub][k]  = h;
    sdh[sub][k] = (1.0f - h * h) * w;
    __syncthreads();

    if (k < TWO_N && m < TPTS) {
        float lat = sb2[k];
        float dl  = 0.0f;
#pragma unroll
        for (int j = 0; j < HH; j++) {
            float w2 = sW2[j * TWO_N + k];
            lat = fmaf(sh[sub][j],  w2, lat);
            dl  = fmaf(sdh[sub][j], w2, dl);
        }
        g_table[m * ROWF + k]         = lat;
        g_table[m * ROWF + TWO_N + k] = dl;
    }
}

// ---------------------------------------------------------------------------
// Kernel 2: expand to per-b residual table.
// Row m of batch b:  s[16] = [a, relu(q-mu)],
//   ur_i = Dq_i - (Ga·a)_i*(mu_i - x_i)   (pos branch of e2, continuous)
//   vr_i = -(Ga·a)_i*mu_i                 (neg branch, smooth)
//   psi  = sum_i e1_i^2,  e1 = Da - g - Pi·x + a   (continuous)
// ---------------------------------------------------------------------------
__global__ void expand_kernel(const float* __restrict__ params_pred) {
    __shared__ float sp[PP];
    const int b   = blockIdx.x;
    const int tid = threadIdx.x;
    if (tid < PP) sp[tid] = params_pred[b * PP + tid];
    __syncthreads();
    const float* g_  = sp;
    const float* mu_ = sp + 8;
    const float* Pi_ = sp + 16;
    const float* Ga_ = sp + 80;

    for (int m = tid; m < TPTS; m += BLK) {
        const float* row = g_table + m * ROWF;
        float a[NN], x[NN], Da[NN], Dq[NN];
#pragma unroll
        for (int i = 0; i < NN; i++) {
            a[i]  = row[i];
            float q = row[NN + i];
            x[i]  = fmaxf(q - mu_[i], 0.0f);
            Da[i] = row[TWO_N + i];
            Dq[i] = row[TWO_N + NN + i];
        }
        float* o = g_btab + ((size_t)b * TPTS + m) * ROWB;
        float psi = 0.0f;
#pragma unroll
        for (int i = 0; i < NN; i++) {
            o[i]      = a[i];
            o[NN + i] = x[i];
            float pix = 0.0f, ga = 0.0f;
#pragma unroll
            for (int j = 0; j < NN; j++) {
                pix = fmaf(Pi_[i * NN + j], x[j], pix);
                ga  = fmaf(Ga_[i * NN + j], a[j], ga);
            }
            float e1 = Da[i] - g_[i] - pix + a[i];
            psi = fmaf(e1, e1, psi);
            o[TWO_N + i]      = Dq[i] - ga * (mu_[i] - x[i]);
            o[TWO_N + NN + i] = -ga * mu_[i];
        }
        o[32] = psi;
    }
}

// ---------------------------------------------------------------------------
// Kernel 3: main loss + fused final reduction (last block)
// ---------------------------------------------------------------------------
__global__ void __launch_bounds__(BLK)
main_kernel(const float* __restrict__ t_in,
            const float* __restrict__ x_target,
            const float* __restrict__ params_pred,
            const float* __restrict__ params_target,
            const float* __restrict__ ic_pred,
            const float* __restrict__ ic_target,
            float* __restrict__ out) {
    __shared__ __align__(16) float s_tab[TPTS * ROWB];   // 47376 B (aliased for final red.)
    __shared__ double s_red[BLK / 32];
    __shared__ double s_sup[40];
    __shared__ int    s_flag;

    const int tid   = threadIdx.x;
    const int b     = blockIdx.x >> 2;
    const int chunk = blockIdx.x & 3;

    // stage this b's residual table (float4)
    {
        const float4* src = (const float4*)(g_btab + (size_t)b * TPTS * ROWB);
        float4*       dst = (float4*)s_tab;
        for (int i = tid; i < TPTS * ROWB4; i += BLK) dst[i] = src[i];
    }
    __syncthreads();

    // prefetch all t values
    float tv[SPT];
#pragma unroll
    for (int it = 0; it < SPT; it++)
        tv[it] = t_in[b * TT + chunk * (SPT * BLK) + it * BLK + tid];

    float acc = 0.0f;

#pragma unroll
    for (int it = 0; it < SPT; it++) {
        const int t = chunk * (SPT * BLK) + it * BLK + tid;

        float u  = tv[it] * (float)TSEG;
        int   i0 = (int)u;
        i0 = min(max(i0, 0), TPTS - 2);
        const float f = u - (float)i0;
        const u64 f2  = pack2(f, f);
        const u64 mf2 = pack2(-f, -f);

        const float4* r0 = (const float4*)s_tab + i0 * ROWB4;
        float V[32];   // s[16] | ur[8] | vr[8]
#pragma unroll
        for (int q = 0; q < 8; q++) {
            F4 a0, a1, r;
            a0.v = r0[q]; a1.v = r0[q + ROWB4];
            r.u[0] = fma2(f2, a1.u[0], fma2(mf2, a0.u[0], a0.u[0]));
            r.u[1] = fma2(f2, a1.u[1], fma2(mf2, a0.u[1], a0.u[1]));
            V[q*4+0] = r.v.x; V[q*4+1] = r.v.y; V[q*4+2] = r.v.z; V[q*4+3] = r.v.w;
        }
        // psi scalar lerp
        float p0 = s_tab[i0 * ROWB + 32];
        float p1 = s_tab[i0 * ROWB + ROWB + 32];
        acc += fmaf(f, p1 - p0, p0);

        // data loss: s vs x_target column t
        const float* xt = x_target + (size_t)b * TWO_N * TT + t;
#pragma unroll
        for (int c = 0; c < TWO_N; c++) {
            float d = V[c] - xt[c * TT];
            acc = fmaf(d, d, acc);
        }

        // gated e2: exact branch select on x>0
#pragma unroll
        for (int i = 0; i < NN; i++) {
            float e2 = (V[NN + i] > 0.0f) ? V[TWO_N + i] : V[TWO_N + NN + i];
            acc = fmaf(e2, e2, acc);
        }
    }

    // supervised slice: 40 elements/block covers B*160 = 40960 exactly
    if (tid < 40) {
        int idx = blockIdx.x * 40 + tid;
        int row = idx / 160;
        int col = idx - row * 160;
        float d;
        if (col < PP) d = params_pred[row * PP + col] - params_target[row * PP + col];
        else          d = ic_pred[row * TWO_N + (col - PP)] - ic_target[row * TWO_N + (col - PP)];
        s_sup[tid] = (double)d * (double)d;
    }

    // deterministic block reduction
    double v = (double)acc;
#pragma unroll
    for (int off = 16; off > 0; off >>= 1)
        v += __shfl_down_sync(0xFFFFFFFFu, v, off);
    if ((tid & 31) == 0) s_red[tid >> 5] = v;
    __syncthreads();
    if (tid == 0) {
        double s = 0.0;
#pragma unroll
        for (int w = 0; w < BLK / 32; w++) s += s_red[w];
        g_partd[blockIdx.x] = s;
        double sp = 0.0;
        for (int j = 0; j < 40; j++) sp += s_sup[j];
        g_parts[blockIdx.x] = sp;
        __threadfence();
        unsigned old = atomicAdd(&g_cnt, 1u);
        s_flag = (old == GRID_MAIN - 1) ? 1 : 0;
    }
    __syncthreads();

    // last block: deterministic final reduction (aliases s_tab)
    if (s_flag) {
        __threadfence();
        double* s1 = (double*)s_tab;
        double* s2 = s1 + (BLK / 32);
        double a = 0.0, c = 0.0;
        for (int i = tid; i < GRID_MAIN; i += BLK) { a += g_partd[i]; c += g_parts[i]; }
#pragma unroll
        for (int off = 16; off > 0; off >>= 1) {
            a += __shfl_down_sync(0xFFFFFFFFu, a, off);
            c += __shfl_down_sync(0xFFFFFFFFu, c, off);
        }
        if ((tid & 31) == 0) { s1[tid >> 5] = a; s2[tid >> 5] = c; }
        __syncthreads();
        if (tid == 0) {
            double t1 = 0.0, t2 = 0.0;
#pragma unroll
            for (int w = 0; w < BLK / 32; w++) { t1 += s1[w]; t2 += s2[w]; }
            double loss = t1 / (double)((size_t)BB * TWO_N * TT)
                        + t2 / (double)(BB * 160);
            out[0] = (float)loss;
            g_cnt  = 0;      // reset for next graph replay
        }
    }
}

// ---------------------------------------------------------------------------
extern "C" void kernel_launch(void* const* d_in, const int* in_sizes, int n_in,
                              void* d_out, int out_size) {
    const float* t_in          = (const float*)d_in[0];
    const float* x_target      = (const float*)d_in[1];
    const float* params_pred   = (const float*)d_in[2];
    const float* params_target = (const float*)d_in[3];
    const float* ic_pred       = (const float*)d_in[4];
    const float* ic_target     = (const float*)d_in[5];
    const float* W1            = (const float*)d_in[6];
    const float* b1            = (const float*)d_in[7];
    const float* W2            = (const float*)d_in[8];
    const float* b2            = (const float*)d_in[9];

    table_kernel<<<(TPTS + 3) / 4, BLK>>>(W1, b1, W2, b2);
    expand_kernel<<<BB, BLK>>>(params_pred);
    main_kernel<<<GRID_MAIN, BLK>>>(t_in, x_target, params_pred, params_target,
                                    ic_pred, ic_target, (float*)d_out);
}

// round 12
// speedup vs baseline: 2.3584x; 1.0232x over previous
#include <cuda_runtime.h>
#include <math.h>

// Problem constants
#define BB     256
#define TT     4096
#define NN     8
#define TWO_N  16
#define PP     144      // 2N + 2N^2
#define HH     64

// latent/dlatent base table over tt in [0,1): 328 segments, lerp err ~4e-6
#define TPTS   329
#define TSEG   328
#define ROWF   36       // base table row stride (floats)

// expanded smem row: s[16] | ur[8] | vr[8] | psi | pad3 = 36 floats
#define ROWB   36
#define ROWB4  9

// 2 blocks per batch row, 256 thr, 8 samples/thread -> single wave of 512
#define GRID_MAIN 512
#define BLK       256
#define SPT       8

__device__ __align__(16) float g_table[TPTS * ROWF];     // latent|dlatent
__device__ double   g_partd[GRID_MAIN];
__device__ double   g_parts[GRID_MAIN];
__device__ unsigned g_cnt = 0;

// ---- packed f32x2 helpers ------------------------------------------------
typedef unsigned long long u64;
__device__ __forceinline__ u64 fma2(u64 a, u64 b, u64 c) {
    u64 d; asm("fma.rn.f32x2 %0, %1, %2, %3;" : "=l"(d) : "l"(a), "l"(b), "l"(c)); return d;
}
__device__ __forceinline__ u64 pack2(float lo, float hi) {
    u64 d; asm("mov.b64 %0, {%1, %2};" : "=l"(d) : "f"(lo), "f"(hi)); return d;
}
union F4 { float4 v; u64 u[2]; };

// ---------------------------------------------------------------------------
// Kernel 1: latent/dlatent vs tt (4 points / 256-thread block)
// ---------------------------------------------------------------------------
__global__ void table_kernel(const float* __restrict__ W1, const float* __restrict__ b1,
                             const float* __restrict__ W2, const float* __restrict__ b2) {
    __shared__ float sW2[HH * TWO_N];
    __shared__ float sb2[TWO_N];
    __shared__ float sh[4][HH];
    __shared__ float sdh[4][HH];
    const int tid = threadIdx.x;
    const int sub = tid >> 6;
    const int k   = tid & 63;
    const int m   = blockIdx.x * 4 + sub;

    for (int i = tid; i < HH * TWO_N; i += BLK) sW2[i] = W2[i];
    if (tid < TWO_N) sb2[tid] = b2[tid];

    float tt = (float)m * (1.0f / (float)TSEG);
    float w  = W1[k];
    float h  = tanhf(fmaf(tt, w, b1[k]));
    sh[sub][k]  = h;
    sdh[sub][k] = (1.0f - h * h) * w;
    __syncthreads();

    if (k < TWO_N && m < TPTS) {
        float lat = sb2[k];
        float dl  = 0.0f;
#pragma unroll
        for (int j = 0; j < HH; j++) {
            float w2 = sW2[j * TWO_N + k];
            lat = fmaf(sh[sub][j],  w2, lat);
            dl  = fmaf(sdh[sub][j], w2, dl);
        }
        g_table[m * ROWF + k]         = lat;
        g_table[m * ROWF + TWO_N + k] = dl;
    }
}

// ---------------------------------------------------------------------------
// Kernel 2: main loss. Each block expands its b's residual table in smem,
// then runs the sample loop. Fused deterministic final reduction.
// ---------------------------------------------------------------------------
__global__ void __launch_bounds__(BLK)
main_kernel(const float* __restrict__ t_in,
            const float* __restrict__ x_target,
            const float* __restrict__ params_pred,
            const float* __restrict__ params_target,
            const float* __restrict__ ic_pred,
            const float* __restrict__ ic_target,
            float* __restrict__ out) {
    __shared__ __align__(16) float s_tab[TPTS * ROWB];   // 47376 B (aliased for final red.)
    __shared__ float  s_par[PP];
    __shared__ double s_red[BLK / 32];
    __shared__ double s_sup[80];
    __shared__ int    s_flag;

    const int tid   = threadIdx.x;
    const int b     = blockIdx.x >> 1;
    const int chunk = blockIdx.x & 1;

    if (tid < PP) s_par[tid] = params_pred[b * PP + tid];
    __syncthreads();

    // ---- in-block expansion: base table (L2-hot) -> residual table in smem
    {
        const float* g_  = s_par;
        const float* mu_ = s_par + 8;
        const float* Pi_ = s_par + 16;
        const float* Ga_ = s_par + 80;
        for (int m = tid; m < TPTS; m += BLK) {
            const float* row = g_table + m * ROWF;
            float a[NN], x[NN], Da[NN], Dq[NN];
#pragma unroll
            for (int i = 0; i < NN; i++) {
                a[i]  = row[i];
                float q = row[NN + i];
                x[i]  = fmaxf(q - mu_[i], 0.0f);
                Da[i] = row[TWO_N + i];
                Dq[i] = row[TWO_N + NN + i];
            }
            float* o = s_tab + m * ROWB;
            float psi = 0.0f;
#pragma unroll
            for (int i = 0; i < NN; i++) {
                o[i]      = a[i];
                o[NN + i] = x[i];
                float pix = 0.0f, ga = 0.0f;
#pragma unroll
                for (int j = 0; j < NN; j++) {
                    pix = fmaf(Pi_[i * NN + j], x[j], pix);
                    ga  = fmaf(Ga_[i * NN + j], a[j], ga);
                }
                float e1 = Da[i] - g_[i] - pix + a[i];
                psi = fmaf(e1, e1, psi);
                o[TWO_N + i]      = Dq[i] - ga * (mu_[i] - x[i]);   // e2 pos branch
                o[TWO_N + NN + i] = -ga * mu_[i];                    // e2 neg branch
            }
            o[32] = psi;
        }
    }
    __syncthreads();

    // ---- sample loop
    float tv[SPT];
#pragma unroll
    for (int it = 0; it < SPT; it++)
        tv[it] = t_in[b * TT + chunk * (SPT * BLK) + it * BLK + tid];

    float acc = 0.0f;

#pragma unroll
    for (int it = 0; it < SPT; it++) {
        const int t = chunk * (SPT * BLK) + it * BLK + tid;

        float u  = tv[it] * (float)TSEG;
        int   i0 = (int)u;
        i0 = min(max(i0, 0), TPTS - 2);
        const float f = u - (float)i0;
        const u64 f2  = pack2(f, f);
        const u64 mf2 = pack2(-f, -f);

        const float4* r0 = (const float4*)s_tab + i0 * ROWB4;
        float V[32];   // s[16] | ur[8] | vr[8]
#pragma unroll
        for (int q = 0; q < 8; q++) {
            F4 a0, a1, r;
            a0.v = r0[q]; a1.v = r0[q + ROWB4];
            r.u[0] = fma2(f2, a1.u[0], fma2(mf2, a0.u[0], a0.u[0]));
            r.u[1] = fma2(f2, a1.u[1], fma2(mf2, a0.u[1], a0.u[1]));
            V[q*4+0] = r.v.x; V[q*4+1] = r.v.y; V[q*4+2] = r.v.z; V[q*4+3] = r.v.w;
        }
        // psi scalar lerp
        float p0 = s_tab[i0 * ROWB + 32];
        float p1 = s_tab[i0 * ROWB + ROWB + 32];
        acc += fmaf(f, p1 - p0, p0);

        // data loss: s vs x_target column t
        const float* xt = x_target + (size_t)b * TWO_N * TT + t;
#pragma unroll
        for (int c = 0; c < TWO_N; c++) {
            float d = V[c] - xt[c * TT];
            acc = fmaf(d, d, acc);
        }

        // gated e2: exact branch select on x>0
#pragma unroll
        for (int i = 0; i < NN; i++) {
            float e2 = (V[NN + i] > 0.0f) ? V[TWO_N + i] : V[TWO_N + NN + i];
            acc = fmaf(e2, e2, acc);
        }
    }

    // supervised slice: 80 elements/block covers B*160 = 40960 exactly
    if (tid < 80) {
        int idx = blockIdx.x * 80 + tid;
        int row = idx / 160;
        int col = idx - row * 160;
        float d;
        if (col < PP) d = params_pred[row * PP + col] - params_target[row * PP + col];
        else          d = ic_pred[row * TWO_N + (col - PP)] - ic_target[row * TWO_N + (col - PP)];
        s_sup[tid] = (double)d * (double)d;
    }

    // deterministic block reduction
    double v = (double)acc;
#pragma unroll
    for (int off = 16; off > 0; off >>= 1)
        v += __shfl_down_sync(0xFFFFFFFFu, v, off);
    if ((tid & 31) == 0) s_red[tid >> 5] = v;
    __syncthreads();
    if (tid == 0) {
        double s = 0.0;
#pragma unroll
        for (int w = 0; w < BLK / 32; w++) s += s_red[w];
        g_partd[blockIdx.x] = s;
        double sp = 0.0;
        for (int j = 0; j < 80; j++) sp += s_sup[j];
        g_parts[blockIdx.x] = sp;
        __threadfence();
        unsigned old = atomicAdd(&g_cnt, 1u);
        s_flag = (old == GRID_MAIN - 1) ? 1 : 0;
    }
    __syncthreads();

    // last block: deterministic final reduction (aliases s_tab)
    if (s_flag) {
        __threadfence();
        double* s1 = (double*)s_tab;
        double* s2 = s1 + (BLK / 32);
        double a = 0.0, c = 0.0;
        for (int i = tid; i < GRID_MAIN; i += BLK) { a += g_partd[i]; c += g_parts[i]; }
#pragma unroll
        for (int off = 16; off > 0; off >>= 1) {
            a += __shfl_down_sync(0xFFFFFFFFu, a, off);
            c += __shfl_down_sync(0xFFFFFFFFu, c, off);
        }
        if ((tid & 31) == 0) { s1[tid >> 5] = a; s2[tid >> 5] = c; }
        __syncthreads();
        if (tid == 0) {
            double t1 = 0.0, t2 = 0.0;
#pragma unroll
            for (int w = 0; w < BLK / 32; w++) { t1 += s1[w]; t2 += s2[w]; }
            double loss = t1 / (double)((size_t)BB * TWO_N * TT)
                        + t2 / (double)(BB * 160);
            out[0] = (float)loss;
            g_cnt  = 0;      // reset for next graph replay
        }
    }
}

// ---------------------------------------------------------------------------
extern "C" void kernel_launch(void* const* d_in, const int* in_sizes, int n_in,
                              void* d_out, int out_size) {
    const float* t_in          = (const float*)d_in[0];
    const float* x_target      = (const float*)d_in[1];
    const float* params_pred   = (const float*)d_in[2];
    const float* params_target = (const float*)d_in[3];
    const float* ic_pred       = (const float*)d_in[4];
    const float* ic_target     = (const float*)d_in[5];
    const float* W1            = (const float*)d_in[6];
    const float* b1            = (const float*)d_in[7];
    const float* W2            = (const float*)d_in[8];
    const float* b2            = (const float*)d_in[9];

    table_kernel<<<(TPTS + 3) / 4, BLK>>>(W1, b1, W2, b2);
    main_kernel<<<GRID_MAIN, BLK>>>(t_in, x_target, params_pred, params_target,
                                    ic_pred, ic_target, (float*)d_out);
}